// round 5
// baseline (speedup 1.0000x reference)
#include <cuda_runtime.h>
#include <cstdint>

#define N_EMBED   1024
#define EMBED_DIM 256
#define N_ROWS    65536
#define MTILE     128
#define NTILE     128
#define KC        64
#define ZQ_ELEMS  (N_ROWS * EMBED_DIM)

typedef unsigned long long u64;

// smem floats: z_s [KC][128] (32KB), e_q [KC][256] duplicated (64KB), e2 [1024], keys 128*u64
#define ZS_FLOATS (KC * 128)
#define EQ_FLOATS (KC * 256)
#define SMEM_FLOATS (ZS_FLOATS + EQ_FLOATS + N_EMBED + 256)
#define SMEM_BYTES (SMEM_FLOATS * 4)

__device__ float g_e2[N_EMBED];

__global__ void e2_kernel(const float* __restrict__ emb) {
    int w = (blockIdx.x * blockDim.x + threadIdx.x) >> 5;
    int lane = threadIdx.x & 31;
    if (w >= N_EMBED) return;
    const float* row = emb + (size_t)w * EMBED_DIM;
    float s = 0.f;
    #pragma unroll
    for (int k = 0; k < EMBED_DIM / 32; k++) {
        float v = row[lane + k * 32];
        s = fmaf(v, v, s);
    }
    #pragma unroll
    for (int off = 16; off; off >>= 1) s += __shfl_xor_sync(0xffffffffu, s, off);
    if (lane == 0) g_e2[w] = s;
}

union Acc { u64 u; float2 f; };

__device__ __forceinline__ void fma2(u64& d, u64 a, u64 b) {
    asm("fma.rn.f32x2 %0, %1, %2, %0;" : "+l"(d) : "l"(a), "l"(b));
}
__device__ __forceinline__ u64 pack_dup(float a) {
    u64 r;
    asm("mov.b64 %0, {%1, %1};" : "=l"(r) : "f"(a));
    return r;
}
__device__ __forceinline__ unsigned ordf(float f) {
    unsigned u = __float_as_uint(f);
    return (u & 0x80000000u) ? ~u : (u | 0x80000000u);
}

__global__ void __launch_bounds__(256, 2)
vq_kernel(const float* __restrict__ z, const float* __restrict__ emb, float* __restrict__ out) {
    extern __shared__ float sm[];
    float* z_s  = sm;                    // [KC][128], col m swizzled: col = m ^ (k&28)
    float* e_q  = sm + ZS_FLOATS;        // [KC][256], quads (e[n]x2, e[n+16]x2) swizzled
    float* e2_s = e_q + EQ_FLOATS;
    u64*   key_s = (u64*)(e2_s + N_EMBED);

    const int tid = threadIdx.x;
    const int tx = tid & 15;             // n direction
    const int ty = tid >> 4;             // m direction: rows ty*8 .. +7
    const int row_base = blockIdx.x * MTILE;
    const int ty8 = ty * 8;
    const int tx4 = tx * 4;

    for (int i = tid; i < N_EMBED; i += 256) e2_s[i] = g_e2[i];

    float best_d[8];
    int   best_n[8];
    #pragma unroll
    for (int i = 0; i < 8; i++) { best_d[i] = __int_as_float(0x7f800000); best_n[i] = 0; }

    for (int nc = 0; nc < N_EMBED / NTILE; nc++) {
        Acc acc[4][8];                   // [m-pair][2*jj+h]
        #pragma unroll
        for (int p = 0; p < 4; p++)
            #pragma unroll
            for (int j = 0; j < 8; j++) acc[p][j].u = 0ull;

        for (int kc = 0; kc < EMBED_DIM / KC; kc++) {
            __syncthreads();
            // ---- stage z chunk [128 m][KC k] transposed, swizzled ----
            {
                const float* zg = z + (size_t)row_base * EMBED_DIM + kc * KC;
                #pragma unroll
                for (int t = 0; t < 8; t++) {
                    int idx = tid + t * 256;      // 0..2047
                    int r  = idx >> 4;            // m row 0..127
                    int k4 = idx & 15;            // k-group
                    float4 v = *(const float4*)(zg + (size_t)r * EMBED_DIM + k4 * 4);
                    int kb = k4 * 4;
                    int s  = kb & 28;             // constant for kb..kb+3
                    int col = r ^ s;
                    z_s[(kb + 0) * 128 + col] = v.x;
                    z_s[(kb + 1) * 128 + col] = v.y;
                    z_s[(kb + 2) * 128 + col] = v.z;
                    z_s[(kb + 3) * 128 + col] = v.w;
                }
            }
            // ---- stage e chunk [128 n][KC k] transposed, DUPLICATED, swizzled ----
            {
                const float* eg = emb + (size_t)(nc * NTILE) * EMBED_DIM + kc * KC;
                #pragma unroll
                for (int t = 0; t < 8; t++) {
                    int idx = tid + t * 256;
                    int n  = idx >> 4;            // code 0..127
                    int k4 = idx & 15;
                    float4 v = *(const float4*)(eg + (size_t)n * EMBED_DIM + k4 * 4);
                    // quad layout: float base = 64*jj + 4*txn + 2*h  (jj=n>>5, h=(n>>4)&1, txn=n&15)
                    int q4 = ((n >> 5) << 6) + ((n & 15) << 2) + (((n >> 4) & 1) << 1);
                    int kb = k4 * 4;
                    int s  = kb & 28;
                    int base = q4 ^ s;            // s only touches bits 2..4; bit1 (h) preserved
                    u64* dst = (u64*)(e_q + (size_t)kb * 256 + base);
                    dst[0]       = pack_dup(v.x);
                    *(u64*)(e_q + (size_t)(kb + 1) * 256 + base) = pack_dup(v.y);
                    *(u64*)(e_q + (size_t)(kb + 2) * 256 + base) = pack_dup(v.z);
                    *(u64*)(e_q + (size_t)(kb + 3) * 256 + base) = pack_dup(v.w);
                }
            }
            __syncthreads();

            // ---- accumulate dot products over this k chunk ----
            #pragma unroll 4
            for (int k = 0; k < KC; k++) {
                const int s = k & 28;
                const float* zk = z_s + (k << 7);
                const float* ek = e_q + (k << 8);
                // a: 2x LDS.128 -> 4 m-pairs (zero MOVs)
                ulonglong2 av0 = *(const ulonglong2*)(zk + ((ty8    ) ^ s));
                ulonglong2 av1 = *(const ulonglong2*)(zk + ((ty8 + 4) ^ s));
                // b: 4x LDS.128 -> 8 duplicated n-pairs
                const int bo = tx4 ^ s;
                ulonglong2 bq0 = *(const ulonglong2*)(ek + bo);
                ulonglong2 bq1 = *(const ulonglong2*)(ek + 64  + bo);
                ulonglong2 bq2 = *(const ulonglong2*)(ek + 128 + bo);
                ulonglong2 bq3 = *(const ulonglong2*)(ek + 192 + bo);
                u64 a[4] = {av0.x, av0.y, av1.x, av1.y};
                u64 b[8] = {bq0.x, bq0.y, bq1.x, bq1.y, bq2.x, bq2.y, bq3.x, bq3.y};
                #pragma unroll
                for (int p = 0; p < 4; p++) {
                    #pragma unroll
                    for (int j = 0; j < 8; j++) fma2(acc[p][j].u, a[p], b[j]);
                }
            }
        }

        // ---- fold this n-chunk into running per-row argmin ----
        #pragma unroll
        for (int p = 0; p < 4; p++) {
            #pragma unroll
            for (int jj = 0; jj < 4; jj++) {
                #pragma unroll
                for (int h = 0; h < 2; h++) {
                    float dot0 = acc[p][2 * jj + h].f.x;   // row ty8 + 2p
                    float dot1 = acc[p][2 * jj + h].f.y;   // row ty8 + 2p + 1
                    int n = nc * NTILE + 32 * jj + 16 * h + tx;
                    float e2v = e2_s[n];
                    float d0 = fmaf(-2.f, dot0, e2v);
                    float d1 = fmaf(-2.f, dot1, e2v);
                    if (d0 < best_d[2 * p])     { best_d[2 * p] = d0;     best_n[2 * p] = n; }
                    if (d1 < best_d[2 * p + 1]) { best_d[2 * p + 1] = d1; best_n[2 * p + 1] = n; }
                }
            }
        }
    }

    // pack ordered keys (tie -> smallest n) and reduce over the 16 tx threads
    u64 keys[8];
    #pragma unroll
    for (int i = 0; i < 8; i++)
        keys[i] = ((u64)ordf(best_d[i]) << 32) | (unsigned)best_n[i];
    #pragma unroll
    for (int off = 1; off < 16; off <<= 1) {
        #pragma unroll
        for (int i = 0; i < 8; i++) {
            u64 o = __shfl_xor_sync(0xffffffffu, keys[i], off);
            if (o < keys[i]) keys[i] = o;
        }
    }
    if (tx == 0) {
        #pragma unroll
        for (int i = 0; i < 8; i++) key_s[ty8 + i] = keys[i];
    }
    __syncthreads();

    // indices (as float) into tail of d_out
    if (tid < 128) {
        unsigned idx = (unsigned)(key_s[tid] & 0xffffffffull);
        out[(size_t)ZQ_ELEMS + row_base + tid] = (float)idx;
    }

    // z_q gather
    float4* outq = (float4*)out;
    for (int it = tid; it < 128 * 64; it += 256) {
        int r  = it >> 6;
        int c4 = it & 63;
        unsigned idx = (unsigned)(key_s[r] & 0xffffffffull);
        float4 v = *(const float4*)(emb + (size_t)idx * EMBED_DIM + c4 * 4);
        outq[(size_t)(row_base + r) * 64 + c4] = v;
    }
}

extern "C" void kernel_launch(void* const* d_in, const int* in_sizes, int n_in,
                              void* d_out, int out_size) {
    const float* z   = (const float*)d_in[0];
    const float* emb = (const float*)d_in[1];
    float* out = (float*)d_out;

    e2_kernel<<<N_EMBED / 8, 256>>>(emb);

    cudaFuncSetAttribute(vq_kernel, cudaFuncAttributeMaxDynamicSharedMemorySize, SMEM_BYTES);
    vq_kernel<<<N_ROWS / MTILE, 256, SMEM_BYTES>>>(z, emb, out);
}

// round 8
// speedup vs baseline: 1.5933x; 1.5933x over previous
#include <cuda_runtime.h>
#include <cstdint>

typedef unsigned long long u64;
typedef unsigned int u32;

#define N_EMBED   1024
#define EMBED_DIM 256
#define N_ROWS    65536
#define MTILE     128
#define NCHUNK    128
#define ZQ_ELEMS  (N_ROWS * EMBED_DIM)

// ---- global scratch: fragment-major pre-split operands ----
// A (z):  [mtile(4096)][kstep(32)][lane(32)*4regs] = 16,777,216 floats each
// B (emb):[kstep(32)][ntile(128)][lane(32)*2regs]  = 262,144 floats each
__device__ float g_zh[16777216];
__device__ float g_zl[16777216];
__device__ float g_eh[262144];
__device__ float g_el[262144];
__device__ float g_e2[N_EMBED];

// ---- smem layout (bytes) ----
#define AH_OFF(b) ((b) * 16384)
#define AL_OFF(b) (32768 + (b) * 16384)
#define BH_OFF(b) (65536 + (b) * 16384)
#define BL_OFF(b) (98304 + (b) * 16384)
#define E2_OFF    131072
#define KEY_OFF   135168
#define SMEM_TOTAL 137216

__device__ __forceinline__ u32 cvt_tf32(float x) {
    u32 r;
    asm("cvt.rna.tf32.f32 %0, %1;" : "=r"(r) : "f"(x));
    return r;
}
__device__ __forceinline__ void split1(float x, float& hi, float& lo) {
    hi = __uint_as_float(cvt_tf32(x));
    lo = __uint_as_float(cvt_tf32(x - hi));
}
__device__ __forceinline__ unsigned ordf(float f) {
    unsigned u = __float_as_uint(f);
    return (u & 0x80000000u) ? ~u : (u | 0x80000000u);
}
__device__ __forceinline__ u32 smem_u32(const void* p) {
    u32 a;
    asm("{ .reg .u64 t; cvta.to.shared.u64 t, %1; cvt.u32.u64 %0, t; }" : "=r"(a) : "l"(p));
    return a;
}
__device__ __forceinline__ void cp16(u32 dst, const void* src) {
    asm volatile("cp.async.cg.shared.global [%0], [%1], 16;" :: "r"(dst), "l"(src));
}
#define CP_COMMIT() asm volatile("cp.async.commit_group;" ::: "memory")
#define CP_WAIT(n)  asm volatile("cp.async.wait_group %0;" :: "n"(n) : "memory")

__device__ __forceinline__ void mma_tf32(float* c, const u32* a, const u32* b) {
    asm volatile(
        "mma.sync.aligned.m16n8k8.row.col.f32.tf32.tf32.f32 "
        "{%0,%1,%2,%3}, {%4,%5,%6,%7}, {%8,%9}, {%0,%1,%2,%3};"
        : "+f"(c[0]), "+f"(c[1]), "+f"(c[2]), "+f"(c[3])
        : "r"(a[0]), "r"(a[1]), "r"(a[2]), "r"(a[3]), "r"(b[0]), "r"(b[1]));
}

// ---------------- pre-split kernels ----------------
// A fragment regs: a0=(g,c) a1=(g+8,c) a2=(g,c+4) a3=(g+8,c+4); g=lane>>2, c=lane&3
__global__ void split_z(const float* __restrict__ z) {
    int idx = blockIdx.x * 256 + threadIdx.x;          // < 4,194,304
    int mtile = idx >> 10, rem = idx & 1023;
    int ks = rem >> 5, lane = rem & 31;
    int g = lane >> 2, c = lane & 3;
    int m0 = mtile * 16 + g, k0 = ks * 8 + c;
    float v0 = z[(size_t)m0 * 256 + k0];
    float v1 = z[(size_t)(m0 + 8) * 256 + k0];
    float v2 = z[(size_t)m0 * 256 + k0 + 4];
    float v3 = z[(size_t)(m0 + 8) * 256 + k0 + 4];
    float4 hi, lo;
    split1(v0, hi.x, lo.x); split1(v1, hi.y, lo.y);
    split1(v2, hi.z, lo.z); split1(v3, hi.w, lo.w);
    *(float4*)&g_zh[(size_t)idx * 4] = hi;
    *(float4*)&g_zl[(size_t)idx * 4] = lo;
}

// B fragment regs: b0=(k=c, n=g) b1=(k=c+4, n=g)
__global__ void split_e(const float* __restrict__ emb) {
    int idx = blockIdx.x * 256 + threadIdx.x;          // < 131,072
    int ks = idx >> 12, rem = idx & 4095;
    int nt = rem >> 5, lane = rem & 31;
    int g = lane >> 2, c = lane & 3;
    int n = nt * 8 + g, k0 = ks * 8 + c;
    float v0 = emb[(size_t)n * 256 + k0];
    float v1 = emb[(size_t)n * 256 + k0 + 4];
    float2 hi, lo;
    split1(v0, hi.x, lo.x); split1(v1, hi.y, lo.y);
    *(float2*)&g_eh[(size_t)idx * 2] = hi;
    *(float2*)&g_el[(size_t)idx * 2] = lo;
}

__global__ void e2_kernel(const float* __restrict__ emb) {
    int w = (blockIdx.x * blockDim.x + threadIdx.x) >> 5;
    int lane = threadIdx.x & 31;
    if (w >= N_EMBED) return;
    const float* row = emb + (size_t)w * EMBED_DIM;
    float s = 0.f;
    #pragma unroll
    for (int k = 0; k < EMBED_DIM / 32; k++) {
        float v = row[lane + k * 32];
        s = fmaf(v, v, s);
    }
    #pragma unroll
    for (int off = 16; off; off >>= 1) s += __shfl_xor_sync(0xffffffffu, s, off);
    if (lane == 0) g_e2[w] = s;
}

// ---------------- main kernel ----------------
__global__ void __launch_bounds__(256, 1)
vq_mma(const float* __restrict__ emb, float* __restrict__ out) {
    extern __shared__ char sm[];
    const u32 sbase = smem_u32(sm);
    const int tid = threadIdx.x;
    const int wid = tid >> 5;
    const int lane = tid & 31;
    const int warp_m = wid >> 1;      // 0..3  (32 rows each)
    const int warp_n = wid & 1;       // 0..1  (64 cols each)
    const int g = lane >> 2, cquad = lane & 3;
    const int row_base = blockIdx.x * MTILE;
    const int rb16 = blockIdx.x * 8;  // base mtile

    float* e2_s = (float*)(sm + E2_OFF);
    for (int i = tid; i < N_EMBED; i += 256) e2_s[i] = g_e2[i];

    // ---- staging helper (pure copy of pre-split fragment data) ----
    auto issue_copy = [&](int nc, int kc, int buf) {
        // A halves: 1024 chunks of 16B each
        #pragma unroll
        for (int i = 0; i < 4; i++) {
            int cch = tid + i * 256;
            int mt = cch >> 7, ks = (cch >> 5) & 3, pos = cch & 31;
            size_t gsrc = ((size_t)(rb16 + mt) * 32 + kc * 4 + ks) * 128 + pos * 4;
            u32 doff = (u32)((ks * 8 + mt) * 512 + pos * 16);
            cp16(sbase + AH_OFF(buf) + doff, g_zh + gsrc);
            cp16(sbase + AL_OFF(buf) + doff, g_zl + gsrc);
        }
        // B halves
        #pragma unroll
        for (int i = 0; i < 4; i++) {
            int cch = tid + i * 256;
            int ks = cch >> 8, nt = (cch >> 4) & 15, pos = cch & 15;
            size_t gsrc = ((size_t)(kc * 4 + ks) * 128 + nc * 16 + nt) * 64 + pos * 4;
            u32 doff = (u32)((ks * 16 + nt) * 256 + pos * 16);
            cp16(sbase + BH_OFF(buf) + doff, g_eh + gsrc);
            cp16(sbase + BL_OFF(buf) + doff, g_el + gsrc);
        }
    };

    float bestd[4];
    int   bestn[4];
    #pragma unroll
    for (int i = 0; i < 4; i++) { bestd[i] = __int_as_float(0x7f800000); bestn[i] = 0; }

    float acc[2][8][4];

    issue_copy(0, 0, 0);
    CP_COMMIT();

    int buf = 0;
    for (int st = 0; st < 64; st++) {
        const int nc = st >> 3, kc = st & 7;
        if (kc == 0) {
            #pragma unroll
            for (int t = 0; t < 2; t++)
                #pragma unroll
                for (int j = 0; j < 8; j++)
                    #pragma unroll
                    for (int q = 0; q < 4; q++) acc[t][j][q] = 0.f;
        }
        if (st < 63) {
            issue_copy((st + 1) >> 3, (st + 1) & 7, buf ^ 1);
            CP_COMMIT();
            CP_WAIT(1);
        } else {
            CP_WAIT(0);
        }
        __syncthreads();

        // ---- 4 ksteps of 3xTF32 MMAs ----
        #pragma unroll
        for (int s = 0; s < 4; s++) {
            u32 ah[2][4], al[2][4];
            #pragma unroll
            for (int t = 0; t < 2; t++) {
                u32 aoff = (u32)((s * 8 + warp_m * 2 + t) * 512 + lane * 16);
                *(uint4*)ah[t] = *(const uint4*)(sm + AH_OFF(buf) + aoff);
                *(uint4*)al[t] = *(const uint4*)(sm + AL_OFF(buf) + aoff);
            }
            u32 bh[8][2], bl[8][2];
            #pragma unroll
            for (int j = 0; j < 8; j++) {
                u32 boff = (u32)((s * 16 + warp_n * 8 + j) * 256 + lane * 8);
                *(uint2*)bh[j] = *(const uint2*)(sm + BH_OFF(buf) + boff);
                *(uint2*)bl[j] = *(const uint2*)(sm + BL_OFF(buf) + boff);
            }
            #pragma unroll
            for (int t = 0; t < 2; t++) {
                #pragma unroll
                for (int j = 0; j < 8; j++) {
                    mma_tf32(acc[t][j], ah[t], bh[j]);
                    mma_tf32(acc[t][j], ah[t], bl[j]);
                    mma_tf32(acc[t][j], al[t], bh[j]);
                }
            }
        }
        __syncthreads();
        buf ^= 1;

        // ---- fold finished n-chunk into per-thread argmin ----
        if (kc == 7) {
            #pragma unroll
            for (int t = 0; t < 2; t++) {
                #pragma unroll
                for (int j = 0; j < 8; j++) {
                    int n0 = nc * NCHUNK + warp_n * 64 + j * 8 + 2 * cquad;
                    float e20 = e2_s[n0], e21 = e2_s[n0 + 1];
                    float d00 = fmaf(-2.f, acc[t][j][0], e20);
                    float d01 = fmaf(-2.f, acc[t][j][1], e21);
                    float d10 = fmaf(-2.f, acc[t][j][2], e20);
                    float d11 = fmaf(-2.f, acc[t][j][3], e21);
                    int s0 = t * 2, s1 = t * 2 + 1;
                    if (d00 < bestd[s0]) { bestd[s0] = d00; bestn[s0] = n0; }
                    if (d01 < bestd[s0]) { bestd[s0] = d01; bestn[s0] = n0 + 1; }
                    if (d10 < bestd[s1]) { bestd[s1] = d10; bestn[s1] = n0; }
                    if (d11 < bestd[s1]) { bestd[s1] = d11; bestn[s1] = n0 + 1; }
                }
            }
        }
    }

    // ---- reduce over the 4 lanes of each quad (same rows, different cols) ----
    u64 keys[4];
    #pragma unroll
    for (int i = 0; i < 4; i++)
        keys[i] = ((u64)ordf(bestd[i]) << 32) | (unsigned)bestn[i];
    #pragma unroll
    for (int off = 1; off < 4; off <<= 1) {
        #pragma unroll
        for (int i = 0; i < 4; i++) {
            u64 o = __shfl_xor_sync(0xffffffffu, keys[i], off);
            if (o < keys[i]) keys[i] = o;
        }
    }
    u64* key_s = (u64*)(sm + KEY_OFF);
    if (cquad == 0) {
        #pragma unroll
        for (int t = 0; t < 2; t++)
            #pragma unroll
            for (int rh = 0; rh < 2; rh++) {
                int row = warp_m * 32 + t * 16 + rh * 8 + g;
                key_s[row * 2 + warp_n] = keys[t * 2 + rh];
            }
    }
    __syncthreads();

    if (tid < 128) {
        u64 k0 = key_s[tid * 2], k1 = key_s[tid * 2 + 1];
        u64 k = (k1 < k0) ? k1 : k0;
        key_s[tid * 2] = k;
        out[(size_t)ZQ_ELEMS + row_base + tid] = (float)(unsigned)(k & 0xffffffffull);
    }
    __syncthreads();

    // ---- z_q gather ----
    float4* outq = (float4*)out;
    for (int it = tid; it < 128 * 64; it += 256) {
        int r  = it >> 6;
        int c4 = it & 63;
        unsigned idx = (unsigned)(key_s[r * 2] & 0xffffffffull);
        float4 v = *(const float4*)(emb + (size_t)idx * EMBED_DIM + c4 * 4);
        outq[(size_t)(row_base + r) * 64 + c4] = v;
    }
}

extern "C" void kernel_launch(void* const* d_in, const int* in_sizes, int n_in,
                              void* d_out, int out_size) {
    const float* z   = (const float*)d_in[0];
    const float* emb = (const float*)d_in[1];
    float* out = (float*)d_out;

    split_z<<<16384, 256>>>(z);
    split_e<<<512, 256>>>(emb);
    e2_kernel<<<N_EMBED / 8, 256>>>(emb);

    cudaFuncSetAttribute(vq_mma, cudaFuncAttributeMaxDynamicSharedMemorySize, SMEM_TOTAL);
    vq_mma<<<N_ROWS / MTILE, 256, SMEM_TOTAL>>>(emb, out);
}

// round 9
// speedup vs baseline: 1.6158x; 1.0141x over previous
#include <cuda_runtime.h>
#include <cstdint>

typedef unsigned long long u64;
typedef unsigned int u32;

#define N_EMBED   1024
#define EMBED_DIM 256
#define N_ROWS    65536
#define MTILE     128
#define NCHUNK    128
#define ZQ_ELEMS  (N_ROWS * EMBED_DIM)

// ---- global scratch: fragment-major pre-split operands ----
// A (z):  [mtile(4096)][kstep(32)][lane(32)*4regs] = 16,777,216 floats each
// B (emb):[kstep(32)][ntile(128)][lane(32)*2regs]  = 262,144 floats each
__device__ float g_zh[16777216];
__device__ float g_zl[16777216];
__device__ float g_eh[262144];
__device__ float g_el[262144];
__device__ float g_e2[N_EMBED];

// ---- smem layout (bytes): 3-stage ring, 64KB per stage ----
#define STG(s)    ((s) * 65536)
#define AH_OFF(s) (STG(s) + 0)
#define AL_OFF(s) (STG(s) + 16384)
#define BH_OFF(s) (STG(s) + 32768)
#define BL_OFF(s) (STG(s) + 49152)
#define E2_OFF    196608
#define KEY_OFF   200704
#define SMEM_TOTAL 202752

__device__ __forceinline__ u32 cvt_tf32(float x) {
    u32 r;
    asm("cvt.rna.tf32.f32 %0, %1;" : "=r"(r) : "f"(x));
    return r;
}
__device__ __forceinline__ void split1(float x, float& hi, float& lo) {
    hi = __uint_as_float(cvt_tf32(x));
    lo = __uint_as_float(cvt_tf32(x - hi));
}
__device__ __forceinline__ unsigned ordf(float f) {
    unsigned u = __float_as_uint(f);
    return (u & 0x80000000u) ? ~u : (u | 0x80000000u);
}
__device__ __forceinline__ u32 smem_u32(const void* p) {
    u32 a;
    asm("{ .reg .u64 t; cvta.to.shared.u64 t, %1; cvt.u32.u64 %0, t; }" : "=r"(a) : "l"(p));
    return a;
}
__device__ __forceinline__ void cp16(u32 dst, const void* src) {
    asm volatile("cp.async.cg.shared.global [%0], [%1], 16;" :: "r"(dst), "l"(src));
}
#define CP_COMMIT() asm volatile("cp.async.commit_group;" ::: "memory")
#define CP_WAIT(n)  asm volatile("cp.async.wait_group %0;" :: "n"(n) : "memory")

__device__ __forceinline__ void mma_tf32(float* c, const u32* a, const u32* b) {
    asm volatile(
        "mma.sync.aligned.m16n8k8.row.col.f32.tf32.tf32.f32 "
        "{%0,%1,%2,%3}, {%4,%5,%6,%7}, {%8,%9}, {%0,%1,%2,%3};"
        : "+f"(c[0]), "+f"(c[1]), "+f"(c[2]), "+f"(c[3])
        : "r"(a[0]), "r"(a[1]), "r"(a[2]), "r"(a[3]), "r"(b[0]), "r"(b[1]));
}

// ---------------- pre-split kernels ----------------
__global__ void split_z(const float* __restrict__ z) {
    int idx = blockIdx.x * 256 + threadIdx.x;          // < 4,194,304
    int mtile = idx >> 10, rem = idx & 1023;
    int ks = rem >> 5, lane = rem & 31;
    int g = lane >> 2, c = lane & 3;
    int m0 = mtile * 16 + g, k0 = ks * 8 + c;
    float v0 = z[(size_t)m0 * 256 + k0];
    float v1 = z[(size_t)(m0 + 8) * 256 + k0];
    float v2 = z[(size_t)m0 * 256 + k0 + 4];
    float v3 = z[(size_t)(m0 + 8) * 256 + k0 + 4];
    float4 hi, lo;
    split1(v0, hi.x, lo.x); split1(v1, hi.y, lo.y);
    split1(v2, hi.z, lo.z); split1(v3, hi.w, lo.w);
    *(float4*)&g_zh[(size_t)idx * 4] = hi;
    *(float4*)&g_zl[(size_t)idx * 4] = lo;
}

__global__ void split_e(const float* __restrict__ emb) {
    int idx = blockIdx.x * 256 + threadIdx.x;          // < 131,072
    int ks = idx >> 12, rem = idx & 4095;
    int nt = rem >> 5, lane = rem & 31;
    int g = lane >> 2, c = lane & 3;
    int n = nt * 8 + g, k0 = ks * 8 + c;
    float v0 = emb[(size_t)n * 256 + k0];
    float v1 = emb[(size_t)n * 256 + k0 + 4];
    float2 hi, lo;
    split1(v0, hi.x, lo.x); split1(v1, hi.y, lo.y);
    *(float2*)&g_eh[(size_t)idx * 2] = hi;
    *(float2*)&g_el[(size_t)idx * 2] = lo;
}

__global__ void e2_kernel(const float* __restrict__ emb) {
    int w = (blockIdx.x * blockDim.x + threadIdx.x) >> 5;
    int lane = threadIdx.x & 31;
    if (w >= N_EMBED) return;
    const float* row = emb + (size_t)w * EMBED_DIM;
    float s = 0.f;
    #pragma unroll
    for (int k = 0; k < EMBED_DIM / 32; k++) {
        float v = row[lane + k * 32];
        s = fmaf(v, v, s);
    }
    #pragma unroll
    for (int off = 16; off; off >>= 1) s += __shfl_xor_sync(0xffffffffu, s, off);
    if (lane == 0) g_e2[w] = s;
}

// ---------------- main kernel ----------------
__global__ void __launch_bounds__(256, 1)
vq_mma(const float* __restrict__ emb, float* __restrict__ out) {
    extern __shared__ char sm[];
    const u32 sbase = smem_u32(sm);
    const int tid = threadIdx.x;
    const int wid = tid >> 5;
    const int lane = tid & 31;
    const int warp_m = wid >> 1;      // 0..3  (32 rows each)
    const int warp_n = wid & 1;       // 0..1  (64 cols each)
    const int g = lane >> 2, cquad = lane & 3;
    const int row_base = blockIdx.x * MTILE;
    const int rb16 = blockIdx.x * 8;  // base mtile

    float* e2_s = (float*)(sm + E2_OFF);
    for (int i = tid; i < N_EMBED; i += 256) e2_s[i] = g_e2[i];

    // staging: pure copy of pre-split fragment data into ring stage `buf`
    auto issue_copy = [&](int st, int buf) {
        const int nc = st >> 3, kc = st & 7;
        #pragma unroll
        for (int i = 0; i < 4; i++) {
            int cch = tid + i * 256;
            int mt = cch >> 7, ks = (cch >> 5) & 3, pos = cch & 31;
            size_t gsrc = ((size_t)(rb16 + mt) * 32 + kc * 4 + ks) * 128 + pos * 4;
            u32 doff = (u32)((ks * 8 + mt) * 512 + pos * 16);
            cp16(sbase + AH_OFF(buf) + doff, g_zh + gsrc);
            cp16(sbase + AL_OFF(buf) + doff, g_zl + gsrc);
        }
        #pragma unroll
        for (int i = 0; i < 4; i++) {
            int cch = tid + i * 256;
            int ks = cch >> 8, nt = (cch >> 4) & 15, pos = cch & 15;
            size_t gsrc = ((size_t)(kc * 4 + ks) * 128 + nc * 16 + nt) * 64 + pos * 4;
            u32 doff = (u32)((ks * 16 + nt) * 256 + pos * 16);
            cp16(sbase + BH_OFF(buf) + doff, g_eh + gsrc);
            cp16(sbase + BL_OFF(buf) + doff, g_el + gsrc);
        }
    };

    float bestd[4];
    int   bestn[4];
    #pragma unroll
    for (int i = 0; i < 4; i++) { bestd[i] = __int_as_float(0x7f800000); bestn[i] = 0; }

    float acc[2][8][4];

    issue_copy(0, 0); CP_COMMIT();
    issue_copy(1, 1); CP_COMMIT();

    for (int st = 0; st < 64; st++) {
        const int nc = st >> 3, kc = st & 7;
        const int buf = st % 3;
        if (kc == 0) {
            #pragma unroll
            for (int t = 0; t < 2; t++)
                #pragma unroll
                for (int j = 0; j < 8; j++)
                    #pragma unroll
                    for (int q = 0; q < 4; q++) acc[t][j][q] = 0.f;
        }
        // wait for stage st's data (2 groups in flight except at the tail)
        if (st < 63) { CP_WAIT(1); } else { CP_WAIT(0); }
        __syncthreads();
        // prefetch stage st+2 into the ring slot drained at stage st-1
        if (st + 2 < 64) { issue_copy(st + 2, (st + 2) % 3); CP_COMMIT(); }

        // ---- 4 ksteps of 3xTF32 MMAs ----
        #pragma unroll
        for (int s = 0; s < 4; s++) {
            u32 ah[2][4], al[2][4];
            #pragma unroll
            for (int t = 0; t < 2; t++) {
                u32 aoff = (u32)((s * 8 + warp_m * 2 + t) * 512 + lane * 16);
                *(uint4*)ah[t] = *(const uint4*)(sm + AH_OFF(buf) + aoff);
                *(uint4*)al[t] = *(const uint4*)(sm + AL_OFF(buf) + aoff);
            }
            u32 bh[8][2], bl[8][2];
            #pragma unroll
            for (int j = 0; j < 8; j++) {
                u32 boff = (u32)((s * 16 + warp_n * 8 + j) * 256 + lane * 8);
                *(uint2*)bh[j] = *(const uint2*)(sm + BH_OFF(buf) + boff);
                *(uint2*)bl[j] = *(const uint2*)(sm + BL_OFF(buf) + boff);
            }
            #pragma unroll
            for (int t = 0; t < 2; t++) {
                #pragma unroll
                for (int j = 0; j < 8; j++) {
                    mma_tf32(acc[t][j], ah[t], bh[j]);
                    mma_tf32(acc[t][j], ah[t], bl[j]);
                    mma_tf32(acc[t][j], al[t], bh[j]);
                }
            }
        }

        // ---- fold finished n-chunk into per-thread argmin ----
        if (kc == 7) {
            #pragma unroll
            for (int t = 0; t < 2; t++) {
                #pragma unroll
                for (int j = 0; j < 8; j++) {
                    int n0 = nc * NCHUNK + warp_n * 64 + j * 8 + 2 * cquad;
                    float e20 = e2_s[n0], e21 = e2_s[n0 + 1];
                    float d00 = fmaf(-2.f, acc[t][j][0], e20);
                    float d01 = fmaf(-2.f, acc[t][j][1], e21);
                    float d10 = fmaf(-2.f, acc[t][j][2], e20);
                    float d11 = fmaf(-2.f, acc[t][j][3], e21);
                    int s0 = t * 2, s1 = t * 2 + 1;
                    if (d00 < bestd[s0]) { bestd[s0] = d00; bestn[s0] = n0; }
                    if (d01 < bestd[s0]) { bestd[s0] = d01; bestn[s0] = n0 + 1; }
                    if (d10 < bestd[s1]) { bestd[s1] = d10; bestn[s1] = n0; }
                    if (d11 < bestd[s1]) { bestd[s1] = d11; bestn[s1] = n0 + 1; }
                }
            }
        }
    }

    // ---- reduce over the 4 lanes of each quad ----
    u64 keys[4];
    #pragma unroll
    for (int i = 0; i < 4; i++)
        keys[i] = ((u64)ordf(bestd[i]) << 32) | (unsigned)bestn[i];
    #pragma unroll
    for (int off = 1; off < 4; off <<= 1) {
        #pragma unroll
        for (int i = 0; i < 4; i++) {
            u64 o = __shfl_xor_sync(0xffffffffu, keys[i], off);
            if (o < keys[i]) keys[i] = o;
        }
    }
    u64* key_s = (u64*)(sm + KEY_OFF);
    if (cquad == 0) {
        #pragma unroll
        for (int t = 0; t < 2; t++)
            #pragma unroll
            for (int rh = 0; rh < 2; rh++) {
                int row = warp_m * 32 + t * 16 + rh * 8 + g;
                key_s[row * 2 + warp_n] = keys[t * 2 + rh];
            }
    }
    __syncthreads();

    if (tid < 128) {
        u64 k0 = key_s[tid * 2], k1 = key_s[tid * 2 + 1];
        u64 k = (k1 < k0) ? k1 : k0;
        key_s[tid * 2] = k;
        out[(size_t)ZQ_ELEMS + row_base + tid] = (float)(unsigned)(k & 0xffffffffull);
    }
    __syncthreads();

    // ---- z_q gather ----
    float4* outq = (float4*)out;
    for (int it = tid; it < 128 * 64; it += 256) {
        int r  = it >> 6;
        int c4 = it & 63;
        unsigned idx = (unsigned)(key_s[r * 2] & 0xffffffffull);
        float4 v = *(const float4*)(emb + (size_t)idx * EMBED_DIM + c4 * 4);
        outq[(size_t)(row_base + r) * 64 + c4] = v;
    }
}

extern "C" void kernel_launch(void* const* d_in, const int* in_sizes, int n_in,
                              void* d_out, int out_size) {
    const float* z   = (const float*)d_in[0];
    const float* emb = (const float*)d_in[1];
    float* out = (float*)d_out;

    split_z<<<16384, 256>>>(z);
    split_e<<<512, 256>>>(emb);
    e2_kernel<<<N_EMBED / 8, 256>>>(emb);

    cudaFuncSetAttribute(vq_mma, cudaFuncAttributeMaxDynamicSharedMemorySize, SMEM_TOTAL);
    vq_mma<<<N_ROWS / MTILE, 256, SMEM_TOTAL>>>(emb, out);
}